// round 16
// baseline (speedup 1.0000x reference)
#include <cuda_runtime.h>
#include <cuda_fp16.h>
#include <cuda_bf16.h>

#define NN 100000
#define EE 1600000
#define GG 256
#define HH 64
#define BN_EPS 1e-5f
#define AST 72   // half-stride of smem tiles (144 B rows, 16B-aligned, conflict-free frags)

// ---------------- scratch (device globals; zero-initialized at load) ----------------
__device__ int     g_deg[NN];
__device__ int     g_total;
__device__ float   g_dinv[NN];
__device__ float4  g_xs[NN];           // dinv * x (3-wide, w=0)
__device__ __half2 g_hsh[NN * 32];     // layer-1 hs (fp16)
__device__ __half2 g_hsh2[NN * 32];    // layer-2 hs (fp16)
__device__ int     g_rowptr[NN];
__device__ int     g_rowend[NN];
__device__ int     g_cursor[NN];
__device__ int     g_csrsrc[EE];
__device__ float   g_gsum[GG * HH];
__device__ int     g_gmax[GG * HH];
__device__ float   g_gcnt[GG];

__device__ __forceinline__ unsigned pack_half2(float a, float b) {
    __half2 h = __float22half2_rn(make_float2(a, b));
    return reinterpret_cast<unsigned&>(h);
}

__device__ __forceinline__ void mma_16816(float* d, unsigned a0, unsigned a1,
                                          unsigned a2, unsigned a3,
                                          unsigned b0, unsigned b1) {
    asm volatile(
        "mma.sync.aligned.m16n8k16.row.col.f32.f16.f16.f32 "
        "{%0,%1,%2,%3}, {%4,%5,%6,%7}, {%8,%9}, {%0,%1,%2,%3};"
        : "+f"(d[0]), "+f"(d[1]), "+f"(d[2]), "+f"(d[3])
        : "r"(a0), "r"(a1), "r"(a2), "r"(a3), "r"(b0), "r"(b1));
}

// ---------------- degree histogram (by dst), 4 edges/thread ----------------
__global__ void k_deg(const int* __restrict__ ei) {
    int i = blockIdx.x * blockDim.x + threadIdx.x;
    if (i < EE / 4) {
        int4 d = ((const int4*)(ei + EE))[i];
        atomicAdd(&g_deg[d.x], 1);
        atomicAdd(&g_deg[d.y], 1);
        atomicAdd(&g_deg[d.z], 1);
        atomicAdd(&g_deg[d.w], 1);
    }
}

// ---------------- CSR slot allocation: warp-aggregated atomic ----------------
__global__ void k_alloc(const float* __restrict__ x) {
    int i = blockIdx.x * blockDim.x + threadIdx.x;
    int lane = threadIdx.x & 31;
    int d = (i < NN) ? g_deg[i] : 0;
    int incl = d;
#pragma unroll
    for (int off = 1; off < 32; off <<= 1) {
        int v = __shfl_up_sync(0xffffffffu, incl, off);
        if (lane >= off) incl += v;
    }
    int total = __shfl_sync(0xffffffffu, incl, 31);
    int base = 0;
    if (lane == 31) base = atomicAdd(&g_total, total);
    base = __shfl_sync(0xffffffffu, base, 31);
    int excl = base + incl - d;
    if (i < NN) {
        g_rowptr[i] = excl;
        g_rowend[i] = excl + d;
        g_cursor[i] = excl;
        float dv = rsqrtf((float)d + 1.0f);
        g_dinv[i] = dv;
        g_xs[i] = make_float4(x[i * 3] * dv, x[i * 3 + 1] * dv, x[i * 3 + 2] * dv, 0.f);
    }
}

// ---------------- CSR fill, 4 edges/thread (+ cleanup of deg/total) ----------------
__global__ void k_csr(const int* __restrict__ ei) {
    int i = blockIdx.x * blockDim.x + threadIdx.x;
    if (i < NN / 4) ((int4*)g_deg)[i] = make_int4(0, 0, 0, 0);
    if (i == 0) g_total = 0;
    if (i < EE / 4) {
        int4 s = ((const int4*)ei)[i];
        int4 d = ((const int4*)(ei + EE))[i];
        g_csrsrc[atomicAdd(&g_cursor[d.x], 1)] = s.x;
        g_csrsrc[atomicAdd(&g_cursor[d.y], 1)] = s.y;
        g_csrsrc[atomicAdd(&g_cursor[d.z], 1)] = s.z;
        g_csrsrc[atomicAdd(&g_cursor[d.w], 1)] = s.w;
    }
}

// ======== FUSED layer0 + GEMM1 (tensor cores): gather3 -> GEMM0+BN+ReLU -> HMMA -> hsh1 ========
// Block = 128 nodes, 512 threads (16 warps).
__global__ void __launch_bounds__(512) k_l0mm1_tc(
        const float* __restrict__ W0,
        const float* __restrict__ b, const float* __restrict__ gm,
        const float* __restrict__ be, const float* __restrict__ rm,
        const float* __restrict__ rv,
        const float* __restrict__ W1) {
    __shared__ __align__(16) __half sA[128 * AST];
    __shared__ __align__(16) __half sW[64 * AST];   // W1^T: sW[c][k]
    __shared__ float sdinv[128];
    __shared__ float sW0[192];
    __shared__ float sbn_sc[64], sbn_sh[64];
    __shared__ float sxa[128][3];
    int t = threadIdx.x, lane = t & 31, warp = t >> 5;
    int nbase = blockIdx.x * 128;

    if (t < 192) sW0[t] = W0[t];
    if (t < 64) {
        float sc = gm[t] * rsqrtf(rv[t] + BN_EPS);
        sbn_sc[t] = sc;
        sbn_sh[t] = (b[t] - rm[t]) * sc + be[t];
    }
    for (int i = t; i < 4096; i += 512) {
        int k = i >> 6, c = i & 63;
        sW[c * AST + k] = __float2half(W1[k * 64 + c]);
    }
    if (t < 128) sdinv[t] = (nbase + t < NN) ? g_dinv[nbase + t] : 0.f;

    // phase 1a: input-space gather, 4 sub-lanes per node (8 nodes/warp in parallel)
    {
        int nl = warp * 8 + (lane >> 2);     // 0..127
        int sub = lane & 3;
        int node = nbase + nl;
        float ax = 0.f, ay = 0.f, az = 0.f;
        if (node < NN) {
            int beg = g_rowptr[node], end = g_rowend[node];
            const int* __restrict__ idx = g_csrsrc;
            for (int k = beg + sub; k < end; k += 4) {
                float4 a = g_xs[idx[k]];
                ax += a.x; ay += a.y; az += a.z;
            }
        }
        ax += __shfl_xor_sync(0xffffffffu, ax, 1);
        ay += __shfl_xor_sync(0xffffffffu, ay, 1);
        az += __shfl_xor_sync(0xffffffffu, az, 1);
        ax += __shfl_xor_sync(0xffffffffu, ax, 2);
        ay += __shfl_xor_sync(0xffffffffu, ay, 2);
        az += __shfl_xor_sync(0xffffffffu, az, 2);
        if (sub == 0 && node < NN) {
            float4 self = g_xs[node];
            float dv = g_dinv[node];
            sxa[nl][0] = (ax + self.x) * dv;
            sxa[nl][1] = (ay + self.y) * dv;
            sxa[nl][2] = (az + self.z) * dv;
        }
    }
    __syncthreads();

    // phase 1b: GEMM0 + BN + ReLU -> fp16 sA ; thread = (node t>>2, 16 cols (t&3)*16)
    {
        int nl = t >> 2;
        int cb = (t & 3) * 16;
        if (nbase + nl < NN) {
            float a0 = sxa[nl][0], a1 = sxa[nl][1], a2 = sxa[nl][2];
            unsigned* dst = (unsigned*)&sA[nl * AST + cb];
#pragma unroll
            for (int p = 0; p < 8; p++) {
                int j0 = cb + 2 * p, j1 = j0 + 1;
                float v0 = a0 * sW0[j0] + a1 * sW0[64 + j0] + a2 * sW0[128 + j0];
                float v1 = a0 * sW0[j1] + a1 * sW0[64 + j1] + a2 * sW0[128 + j1];
                v0 = fmaxf(fmaf(v0, sbn_sc[j0], sbn_sh[j0]), 0.f);
                v1 = fmaxf(fmaf(v1, sbn_sc[j1], sbn_sh[j1]), 0.f);
                dst[p] = pack_half2(v0, v1);
            }
        }
    }
    __syncthreads();

    // phase 2: tensor-core GEMM1 -> hsh1 (scaled by dinv)
    int g = lane >> 2, tig = lane & 3;
    int mt = warp & 7, nt2 = warp >> 3;
    float acc[4][4];
#pragma unroll
    for (int nt = 0; nt < 4; nt++) { acc[nt][0] = acc[nt][1] = acc[nt][2] = acc[nt][3] = 0.f; }
    int r0 = mt * 16 + g;
#pragma unroll
    for (int kt = 0; kt < 4; kt++) {
        int kb = kt * 16 + 2 * tig;
        unsigned a0 = *(const unsigned*)&sA[r0 * AST + kb];
        unsigned a1 = *(const unsigned*)&sA[(r0 + 8) * AST + kb];
        unsigned a2 = *(const unsigned*)&sA[r0 * AST + kb + 8];
        unsigned a3 = *(const unsigned*)&sA[(r0 + 8) * AST + kb + 8];
#pragma unroll
        for (int nt = 0; nt < 4; nt++) {
            int col = nt2 * 32 + nt * 8 + g;
            unsigned b0 = *(const unsigned*)&sW[col * AST + kb];
            unsigned b1 = *(const unsigned*)&sW[col * AST + kb + 8];
            mma_16816(acc[nt], a0, a1, a2, a3, b0, b1);
        }
    }
    __syncthreads();   // all sA reads done; reuse sA as output tile
    float dv0 = sdinv[r0], dv1 = sdinv[r0 + 8];
#pragma unroll
    for (int nt = 0; nt < 4; nt++) {
        int cb = nt2 * 32 + nt * 8 + 2 * tig;
        *(unsigned*)&sA[r0 * AST + cb]       = pack_half2(acc[nt][0] * dv0, acc[nt][1] * dv0);
        *(unsigned*)&sA[(r0 + 8) * AST + cb] = pack_half2(acc[nt][2] * dv1, acc[nt][3] * dv1);
    }
    __syncthreads();
    for (int i = t; i < 1024; i += 512) {
        int n = i >> 3, ch = i & 7;
        if (nbase + n < NN)
            ((uint4*)g_hsh)[(nbase + n) * 8 + ch] = *(const uint4*)&sA[n * AST + ch * 8];
    }
}

// ---------------- FUSED gather(l1) + GEMM2 (tensor cores): hsh1 -> hsh2 ----------------
__global__ void __launch_bounds__(512) k_g1mm2_tc(
        const float* __restrict__ b, const float* __restrict__ gm,
        const float* __restrict__ be, const float* __restrict__ rm,
        const float* __restrict__ rv,
        const float* __restrict__ W2) {
    __shared__ __align__(16) __half sA[128 * AST];
    __shared__ __align__(16) __half sW[64 * AST];
    __shared__ float sdinv[128];
    int t = threadIdx.x, lane = t & 31, warp = t >> 5;
    int nbase = blockIdx.x * 128;

    for (int i = t; i < 4096; i += 512) {
        int k = i >> 6, c = i & 63;
        sW[c * AST + k] = __float2half(W2[k * 64 + c]);
    }
    if (t < 128) sdinv[t] = (nbase + t < NN) ? g_dinv[nbase + t] : 0.f;

    int j = lane * 2;
    float scx = gm[j] * rsqrtf(rv[j] + BN_EPS);
    float scy = gm[j + 1] * rsqrtf(rv[j + 1] + BN_EPS);
    float shx = (b[j] - rm[j]) * scx + be[j];
    float shy = (b[j + 1] - rm[j + 1]) * scy + be[j + 1];

    const __half2* __restrict__ hs2 = g_hsh;

#pragma unroll
    for (int i = 0; i < 8; i++) {
        int nl = warp * 8 + i;
        int node = nbase + nl;
        if (node >= NN) break;
        float2 acc = __half22float2(hs2[node * 32 + lane]);   // self-loop term
        int beg = g_rowptr[node];
        int m = g_rowend[node] - beg;
        const int* __restrict__ idx = g_csrsrc + beg;
        for (int base = 0; base < m; base += 32) {
            int rem = m - base;
            int cnt = (rem < 32) ? rem : 32;
            int myidx = (lane < cnt) ? idx[base + lane] : 0;
            int k = 0;
            for (; k + 4 <= cnt; k += 4) {
                int s0 = __shfl_sync(0xffffffffu, myidx, k);
                int s1 = __shfl_sync(0xffffffffu, myidx, k + 1);
                int s2 = __shfl_sync(0xffffffffu, myidx, k + 2);
                int s3 = __shfl_sync(0xffffffffu, myidx, k + 3);
                float2 v0 = __half22float2(hs2[s0 * 32 + lane]);
                float2 v1 = __half22float2(hs2[s1 * 32 + lane]);
                float2 v2 = __half22float2(hs2[s2 * 32 + lane]);
                float2 v3 = __half22float2(hs2[s3 * 32 + lane]);
                acc.x += (v0.x + v1.x) + (v2.x + v3.x);
                acc.y += (v0.y + v1.y) + (v2.y + v3.y);
            }
            for (; k < cnt; k++) {
                int s = __shfl_sync(0xffffffffu, myidx, k);
                float2 v = __half22float2(hs2[s * 32 + lane]);
                acc.x += v.x; acc.y += v.y;
            }
        }
        float dv = g_dinv[node];
        float ox = fmaxf(fmaf(acc.x * dv, scx, shx), 0.f);
        float oy = fmaxf(fmaf(acc.y * dv, scy, shy), 0.f);
        *(unsigned*)&sA[nl * AST + j] = pack_half2(ox, oy);
    }
    __syncthreads();

    int g = lane >> 2, tig = lane & 3;
    int mt = warp & 7, nt2 = warp >> 3;
    float acc[4][4];
#pragma unroll
    for (int nt = 0; nt < 4; nt++) { acc[nt][0] = acc[nt][1] = acc[nt][2] = acc[nt][3] = 0.f; }
    int r0 = mt * 16 + g;
#pragma unroll
    for (int kt = 0; kt < 4; kt++) {
        int kb = kt * 16 + 2 * tig;
        unsigned a0 = *(const unsigned*)&sA[r0 * AST + kb];
        unsigned a1 = *(const unsigned*)&sA[(r0 + 8) * AST + kb];
        unsigned a2 = *(const unsigned*)&sA[r0 * AST + kb + 8];
        unsigned a3 = *(const unsigned*)&sA[(r0 + 8) * AST + kb + 8];
#pragma unroll
        for (int nt = 0; nt < 4; nt++) {
            int col = nt2 * 32 + nt * 8 + g;
            unsigned b0 = *(const unsigned*)&sW[col * AST + kb];
            unsigned b1 = *(const unsigned*)&sW[col * AST + kb + 8];
            mma_16816(acc[nt], a0, a1, a2, a3, b0, b1);
        }
    }
    __syncthreads();
    float dv0 = sdinv[r0], dv1 = sdinv[r0 + 8];
#pragma unroll
    for (int nt = 0; nt < 4; nt++) {
        int cb = nt2 * 32 + nt * 8 + 2 * tig;
        *(unsigned*)&sA[r0 * AST + cb]       = pack_half2(acc[nt][0] * dv0, acc[nt][1] * dv0);
        *(unsigned*)&sA[(r0 + 8) * AST + cb] = pack_half2(acc[nt][2] * dv1, acc[nt][3] * dv1);
    }
    __syncthreads();
    for (int i = t; i < 1024; i += 512) {
        int n = i >> 3, ch = i & 7;
        if (nbase + n < NN)
            ((uint4*)g_hsh2)[(nbase + n) * 8 + ch] = *(const uint4*)&sA[n * AST + ch * 8];
    }
}

// ---------------- gather layer 3 + FUSED POOLING (reads hsh2) ----------------
__global__ void __launch_bounds__(256) k_gather2(
        const int* __restrict__ bidx,
        const float* __restrict__ b, const float* __restrict__ gm,
        const float* __restrict__ be, const float* __restrict__ rm,
        const float* __restrict__ rv) {
    __shared__ float sval[8][64];
    __shared__ int   sgid[8];
    int lane = threadIdx.x & 31;
    int w = threadIdx.x >> 5;
    int node = blockIdx.x * 8 + w;

    int j = lane * 2;
    float scx = gm[j] * rsqrtf(rv[j] + BN_EPS);
    float scy = gm[j + 1] * rsqrtf(rv[j + 1] + BN_EPS);
    float shx = (b[j] - rm[j]) * scx + be[j];
    float shy = (b[j + 1] - rm[j + 1]) * scy + be[j + 1];

    const __half2* __restrict__ hs2 = g_hsh2;
    float2 acc = __half22float2(hs2[node * 32 + lane]);

    int beg = g_rowptr[node];
    int m = g_rowend[node] - beg;
    const int* __restrict__ idx = g_csrsrc + beg;

    for (int base = 0; base < m; base += 32) {
        int rem = m - base;
        int cnt = (rem < 32) ? rem : 32;
        int myidx = (lane < cnt) ? idx[base + lane] : 0;
        int k = 0;
        for (; k + 4 <= cnt; k += 4) {
            int s0 = __shfl_sync(0xffffffffu, myidx, k);
            int s1 = __shfl_sync(0xffffffffu, myidx, k + 1);
            int s2 = __shfl_sync(0xffffffffu, myidx, k + 2);
            int s3 = __shfl_sync(0xffffffffu, myidx, k + 3);
            float2 v0 = __half22float2(hs2[s0 * 32 + lane]);
            float2 v1 = __half22float2(hs2[s1 * 32 + lane]);
            float2 v2 = __half22float2(hs2[s2 * 32 + lane]);
            float2 v3 = __half22float2(hs2[s3 * 32 + lane]);
            acc.x += (v0.x + v1.x) + (v2.x + v3.x);
            acc.y += (v0.y + v1.y) + (v2.y + v3.y);
        }
        for (; k < cnt; k++) {
            int s = __shfl_sync(0xffffffffu, myidx, k);
            float2 v = __half22float2(hs2[s * 32 + lane]);
            acc.x += v.x; acc.y += v.y;
        }
    }

    float dv = g_dinv[node];
    sval[w][j]     = fmaxf(fmaf(acc.x * dv, scx, shx), 0.f);
    sval[w][j + 1] = fmaxf(fmaf(acc.y * dv, scy, shy), 0.f);
    if (lane == 0) sgid[w] = bidx[node];
    __syncthreads();

    int gid = sgid[w];
    bool leader = (w == 0) || (sgid[w - 1] != gid);
    if (leader) {
        float sx = 0.f, sy = 0.f, mxx = 0.f, mxy = 0.f;
        int c = 0;
        for (int s2 = w; s2 < 8 && sgid[s2] == gid; s2++) {
            float vx = sval[s2][j], vy = sval[s2][j + 1];
            sx += vx; sy += vy;
            mxx = fmaxf(mxx, vx); mxy = fmaxf(mxy, vy);
            c++;
        }
        atomicAdd(&g_gsum[gid * 64 + j], sx);
        atomicAdd(&g_gsum[gid * 64 + j + 1], sy);
        atomicMax(&g_gmax[gid * 64 + j], __float_as_int(mxx));
        atomicMax(&g_gmax[gid * 64 + j + 1], __float_as_int(mxy));
        if (lane == 0) atomicAdd(&g_gcnt[gid], (float)c);
    }
}

// ---------------- MLP head (+ cleanup of pooling accumulators) ----------------
__global__ void k_mlp(const float* __restrict__ mW1, const float* __restrict__ mb1,
                      const float* __restrict__ mW2, const float* __restrict__ mb2,
                      const float* __restrict__ mW3, const float* __restrict__ mb3,
                      float* __restrict__ out) {
    __shared__ float xg[128];
    __shared__ float h1[32];
    __shared__ float h2[16];
    int g = blockIdx.x;
    int t = threadIdx.x;                // 32 threads
    float cnt = fmaxf(g_gcnt[g], 1.f);
    for (int j = t; j < 64; j += 32) {
        xg[j]      = g_gsum[g * 64 + j] / cnt;
        xg[64 + j] = __int_as_float(g_gmax[g * 64 + j]);
    }
    __syncthreads();
    for (int j = t; j < 64; j += 32) {
        g_gsum[g * 64 + j] = 0.f;
        g_gmax[g * 64 + j] = 0;
    }
    if (t == 0) g_gcnt[g] = 0.f;
    {
        float acc = mb1[t];
        for (int k = 0; k < 128; k++) acc += xg[k] * mW1[k * 32 + t];
        h1[t] = fmaxf(acc, 0.f);
    }
    __syncthreads();
    if (t < 16) {
        float acc = mb2[t];
        for (int k = 0; k < 32; k++) acc += h1[k] * mW2[k * 16 + t];
        h2[t] = fmaxf(acc, 0.f);
    }
    __syncthreads();
    if (t == 0) {
        float acc = mb3[0];
        for (int k = 0; k < 16; k++) acc += h2[k] * mW3[k];
        out[g] = acc;
    }
}

extern "C" void kernel_launch(void* const* d_in, const int* in_sizes, int n_in,
                              void* d_out, int out_size) {
    const float* x    = (const float*)d_in[0];
    const int*   ei   = (const int*)  d_in[1];
    const int*   bidx = (const int*)  d_in[2];
    const float* W[3]  = {(const float*)d_in[3],  (const float*)d_in[9],  (const float*)d_in[15]};
    const float* b[3]  = {(const float*)d_in[4],  (const float*)d_in[10], (const float*)d_in[16]};
    const float* gm[3] = {(const float*)d_in[5],  (const float*)d_in[11], (const float*)d_in[17]};
    const float* be[3] = {(const float*)d_in[6],  (const float*)d_in[12], (const float*)d_in[18]};
    const float* rm[3] = {(const float*)d_in[7],  (const float*)d_in[13], (const float*)d_in[19]};
    const float* rv[3] = {(const float*)d_in[8],  (const float*)d_in[14], (const float*)d_in[20]};
    const float* mW1 = (const float*)d_in[21];
    const float* mb1 = (const float*)d_in[22];
    const float* mW2 = (const float*)d_in[23];
    const float* mb2 = (const float*)d_in[24];
    const float* mW3 = (const float*)d_in[25];
    const float* mb3 = (const float*)d_in[26];
    float* out = (float*)d_out;

    const int T = 256;
    int deg4Blocks = (EE / 4 + T - 1) / T;
    int nBlocks    = (NN + T - 1) / T;
    int tcBlocks   = (NN + 127) / 128;
    int gatBlocks  = NN / 8;            // NN % 8 == 0

    k_deg<<<deg4Blocks, T>>>(ei);
    k_alloc<<<nBlocks, T>>>(x);
    k_csr<<<deg4Blocks, T>>>(ei);

    k_l0mm1_tc<<<tcBlocks, 512>>>(W[0], b[0], gm[0], be[0], rm[0], rv[0], W[1]);
    k_g1mm2_tc<<<tcBlocks, 512>>>(b[1], gm[1], be[1], rm[1], rv[1], W[2]);
    k_gather2<<<gatBlocks, T>>>(bidx, b[2], gm[2], be[2], rm[2], rv[2]);

    k_mlp<<<GG, 32>>>(mW1, mb1, mW2, mb2, mW3, mb3, out);
}

// round 17
// speedup vs baseline: 1.5569x; 1.5569x over previous
#include <cuda_runtime.h>
#include <cuda_fp16.h>
#include <cuda_bf16.h>

#define NN 100000
#define EE 1600000
#define GG 256
#define HH 64
#define BN_EPS 1e-5f
#define AST 72   // half-stride of smem tiles (144 B rows, 16B-aligned, conflict-free frags)

// ---------------- scratch (device globals; zero-initialized at load) ----------------
__device__ int     g_deg[NN];
__device__ int     g_total;
__device__ float   g_dinv[NN];
__device__ float4  g_xs[NN];           // dinv * x (3-wide, w=0)
__device__ __half  g_xh[NN * 64];      // fp16 activations (written by layer0, then gatherM)
__device__ __half2 g_hsh[NN * 32];     // layer-1 hs (fp16)
__device__ __half2 g_hsh2[NN * 32];    // layer-2 hs (fp16)
__device__ int     g_rowptr[NN];
__device__ int     g_rowend[NN];
__device__ int     g_cursor[NN];
__device__ int     g_csrsrc[EE];
__device__ float   g_gsum[GG * HH];
__device__ int     g_gmax[GG * HH];
__device__ float   g_gcnt[GG];

__device__ __forceinline__ unsigned pack_half2(float a, float b) {
    __half2 h = __float22half2_rn(make_float2(a, b));
    return reinterpret_cast<unsigned&>(h);
}

__device__ __forceinline__ void mma_16816(float* d, unsigned a0, unsigned a1,
                                          unsigned a2, unsigned a3,
                                          unsigned b0, unsigned b1) {
    asm volatile(
        "mma.sync.aligned.m16n8k16.row.col.f32.f16.f16.f32 "
        "{%0,%1,%2,%3}, {%4,%5,%6,%7}, {%8,%9}, {%0,%1,%2,%3};"
        : "+f"(d[0]), "+f"(d[1]), "+f"(d[2]), "+f"(d[3])
        : "r"(a0), "r"(a1), "r"(a2), "r"(a3), "r"(b0), "r"(b1));
}

// ---------------- degree histogram (by dst), 4 edges/thread ----------------
__global__ void k_deg(const int* __restrict__ ei) {
    int i = blockIdx.x * blockDim.x + threadIdx.x;
    if (i < EE / 4) {
        int4 d = ((const int4*)(ei + EE))[i];
        atomicAdd(&g_deg[d.x], 1);
        atomicAdd(&g_deg[d.y], 1);
        atomicAdd(&g_deg[d.z], 1);
        atomicAdd(&g_deg[d.w], 1);
    }
}

// ---------------- CSR slot allocation: warp-aggregated atomic ----------------
__global__ void k_alloc(const float* __restrict__ x) {
    int i = blockIdx.x * blockDim.x + threadIdx.x;
    int lane = threadIdx.x & 31;
    int d = (i < NN) ? g_deg[i] : 0;
    int incl = d;
#pragma unroll
    for (int off = 1; off < 32; off <<= 1) {
        int v = __shfl_up_sync(0xffffffffu, incl, off);
        if (lane >= off) incl += v;
    }
    int total = __shfl_sync(0xffffffffu, incl, 31);
    int base = 0;
    if (lane == 31) base = atomicAdd(&g_total, total);
    base = __shfl_sync(0xffffffffu, base, 31);
    int excl = base + incl - d;
    if (i < NN) {
        g_rowptr[i] = excl;
        g_rowend[i] = excl + d;
        g_cursor[i] = excl;
        float dv = rsqrtf((float)d + 1.0f);
        g_dinv[i] = dv;
        g_xs[i] = make_float4(x[i * 3] * dv, x[i * 3 + 1] * dv, x[i * 3 + 2] * dv, 0.f);
    }
}

// ---------------- CSR fill, 4 edges/thread (+ cleanup of deg/total) ----------------
__global__ void k_csr(const int* __restrict__ ei) {
    int i = blockIdx.x * blockDim.x + threadIdx.x;
    if (i < NN / 4) ((int4*)g_deg)[i] = make_int4(0, 0, 0, 0);
    if (i == 0) g_total = 0;
    if (i < EE / 4) {
        int4 s = ((const int4*)ei)[i];
        int4 d = ((const int4*)(ei + EE))[i];
        g_csrsrc[atomicAdd(&g_cursor[d.x], 1)] = s.x;
        g_csrsrc[atomicAdd(&g_cursor[d.y], 1)] = s.y;
        g_csrsrc[atomicAdd(&g_cursor[d.z], 1)] = s.z;
        g_csrsrc[atomicAdd(&g_cursor[d.w], 1)] = s.w;
    }
}

// ---------------- layer 0: input-space gather + GEMM0 + BN + ReLU -> g_xh (fp16) ----------------
__global__ void __launch_bounds__(256) k_layer0(const float* __restrict__ W0,
        const float* __restrict__ b, const float* __restrict__ gm,
        const float* __restrict__ be, const float* __restrict__ rm,
        const float* __restrict__ rv) {
    __shared__ float sW[192];
    __shared__ float sxa[64][3];
    int t = threadIdx.x;
    int lane = t & 31;
    int warp = t >> 5;
    if (t < 192) sW[t] = W0[t];

    int nl = warp * 8 + (lane >> 2);
    int sub = lane & 3;
    int n = blockIdx.x * 64 + nl;

    float ax = 0.f, ay = 0.f, az = 0.f;
    if (n < NN) {
        int beg = g_rowptr[n], end = g_rowend[n];
        const int* __restrict__ idx = g_csrsrc;
        for (int k = beg + sub; k < end; k += 4) {
            float4 a = g_xs[idx[k]];
            ax += a.x; ay += a.y; az += a.z;
        }
    }
    ax += __shfl_xor_sync(0xffffffffu, ax, 1);
    ay += __shfl_xor_sync(0xffffffffu, ay, 1);
    az += __shfl_xor_sync(0xffffffffu, az, 1);
    ax += __shfl_xor_sync(0xffffffffu, ax, 2);
    ay += __shfl_xor_sync(0xffffffffu, ay, 2);
    az += __shfl_xor_sync(0xffffffffu, az, 2);
    if (sub == 0 && n < NN) {
        float4 self = g_xs[n];
        float dv = g_dinv[n];
        sxa[nl][0] = (ax + self.x) * dv;
        sxa[nl][1] = (ay + self.y) * dv;
        sxa[nl][2] = (az + self.z) * dv;
    }
    __syncthreads();

    int q = t & 15;
    int j = q * 4;
    float4 sc, sh;
    sc.x = gm[j] * rsqrtf(rv[j] + BN_EPS);
    sc.y = gm[j + 1] * rsqrtf(rv[j + 1] + BN_EPS);
    sc.z = gm[j + 2] * rsqrtf(rv[j + 2] + BN_EPS);
    sc.w = gm[j + 3] * rsqrtf(rv[j + 3] + BN_EPS);
    sh.x = (b[j] - rm[j]) * sc.x + be[j];
    sh.y = (b[j + 1] - rm[j + 1]) * sc.y + be[j + 1];
    sh.z = (b[j + 2] - rm[j + 2]) * sc.z + be[j + 2];
    sh.w = (b[j + 3] - rm[j + 3]) * sc.w + be[j + 3];
    float w0x = sW[j],       w0y = sW[j + 1],       w0z = sW[j + 2],       w0w = sW[j + 3];
    float w1x = sW[64 + j],  w1y = sW[64 + j + 1],  w1z = sW[64 + j + 2],  w1w = sW[64 + j + 3];
    float w2x = sW[128 + j], w2y = sW[128 + j + 1], w2z = sW[128 + j + 2], w2w = sW[128 + j + 3];
#pragma unroll
    for (int r = 0; r < 4; r++) {
        int nl2 = r * 16 + (t >> 4);
        int gn = blockIdx.x * 64 + nl2;
        if (gn >= NN) break;
        float a0 = sxa[nl2][0], a1 = sxa[nl2][1], a2 = sxa[nl2][2];
        float4 o;
        o.x = fmaxf(fmaf(a0 * w0x + a1 * w1x + a2 * w2x, sc.x, sh.x), 0.f);
        o.y = fmaxf(fmaf(a0 * w0y + a1 * w1y + a2 * w2y, sc.y, sh.y), 0.f);
        o.z = fmaxf(fmaf(a0 * w0z + a1 * w1z + a2 * w2z, sc.z, sh.z), 0.f);
        o.w = fmaxf(fmaf(a0 * w0w + a1 * w1w + a2 * w2w, sc.w, sh.w), 0.f);
        uint2 o2 = make_uint2(pack_half2(o.x, o.y), pack_half2(o.z, o.w));
        ((uint2*)g_xh)[gn * 16 + q] = o2;
    }
}

// ---------------- tensor-core GEMM: g_xh @ W -> (hsh1 | hsh2), scaled by dinv ----------------
// Block = 128 nodes, 512 threads (16 warps). which: 0 -> g_hsh, 1 -> g_hsh2.
__global__ void __launch_bounds__(512) k_mm_tc(const float* __restrict__ W, int which) {
    __shared__ __align__(16) __half sA[128 * AST];
    __shared__ __align__(16) __half sW[64 * AST];   // W^T: sW[c][k]
    __shared__ float sdinv[128];
    int t = threadIdx.x, lane = t & 31, warp = t >> 5;
    int nbase = blockIdx.x * 128;

    for (int i = t; i < 1024; i += 512) {
        int n = i >> 3, ch = i & 7;
        uint4 v = make_uint4(0u, 0u, 0u, 0u);
        if (nbase + n < NN) v = ((const uint4*)g_xh)[(nbase + n) * 8 + ch];
        *(uint4*)&sA[n * AST + ch * 8] = v;
    }
    for (int i = t; i < 4096; i += 512) {
        int k = i >> 6, c = i & 63;
        sW[c * AST + k] = __float2half(W[k * 64 + c]);
    }
    if (t < 128) sdinv[t] = (nbase + t < NN) ? g_dinv[nbase + t] : 0.f;
    __syncthreads();

    int g = lane >> 2, tig = lane & 3;
    int mt = warp & 7, nt2 = warp >> 3;
    float acc[4][4];
#pragma unroll
    for (int nt = 0; nt < 4; nt++) { acc[nt][0] = acc[nt][1] = acc[nt][2] = acc[nt][3] = 0.f; }
    int r0 = mt * 16 + g;
#pragma unroll
    for (int kt = 0; kt < 4; kt++) {
        int kb = kt * 16 + 2 * tig;
        unsigned a0 = *(const unsigned*)&sA[r0 * AST + kb];
        unsigned a1 = *(const unsigned*)&sA[(r0 + 8) * AST + kb];
        unsigned a2 = *(const unsigned*)&sA[r0 * AST + kb + 8];
        unsigned a3 = *(const unsigned*)&sA[(r0 + 8) * AST + kb + 8];
#pragma unroll
        for (int nt = 0; nt < 4; nt++) {
            int col = nt2 * 32 + nt * 8 + g;
            unsigned b0 = *(const unsigned*)&sW[col * AST + kb];
            unsigned b1 = *(const unsigned*)&sW[col * AST + kb + 8];
            mma_16816(acc[nt], a0, a1, a2, a3, b0, b1);
        }
    }
    __syncthreads();   // all sA reads done; reuse sA as output tile
    float dv0 = sdinv[r0], dv1 = sdinv[r0 + 8];
#pragma unroll
    for (int nt = 0; nt < 4; nt++) {
        int cb = nt2 * 32 + nt * 8 + 2 * tig;
        *(unsigned*)&sA[r0 * AST + cb]       = pack_half2(acc[nt][0] * dv0, acc[nt][1] * dv0);
        *(unsigned*)&sA[(r0 + 8) * AST + cb] = pack_half2(acc[nt][2] * dv1, acc[nt][3] * dv1);
    }
    __syncthreads();
    uint4* dst = (which == 0) ? (uint4*)g_hsh : (uint4*)g_hsh2;
    for (int i = t; i < 1024; i += 512) {
        int n = i >> 3, ch = i & 7;
        if (nbase + n < NN)
            dst[(nbase + n) * 8 + ch] = *(const uint4*)&sA[n * AST + ch * 8];
    }
}

// ---------------- gather (layer 1): hsh1 -> BN + ReLU -> g_xh (fp16) ----------------
// 8 nodes/block, 256 threads; warp per node, lane owns cols j, j+1.
__global__ void __launch_bounds__(256) k_gatherM(
        const float* __restrict__ b, const float* __restrict__ gm,
        const float* __restrict__ be, const float* __restrict__ rm,
        const float* __restrict__ rv) {
    int lane = threadIdx.x & 31;
    int node = blockIdx.x * 8 + (threadIdx.x >> 5);
    if (node >= NN) return;

    int j = lane * 2;
    float scx = gm[j] * rsqrtf(rv[j] + BN_EPS);
    float scy = gm[j + 1] * rsqrtf(rv[j + 1] + BN_EPS);
    float shx = (b[j] - rm[j]) * scx + be[j];
    float shy = (b[j + 1] - rm[j + 1]) * scy + be[j + 1];

    const __half2* __restrict__ hs2 = g_hsh;
    float2 acc = __half22float2(hs2[node * 32 + lane]);   // self-loop term

    int beg = g_rowptr[node];
    int m = g_rowend[node] - beg;
    const int* __restrict__ idx = g_csrsrc + beg;

    for (int base = 0; base < m; base += 32) {
        int rem = m - base;
        int cnt = (rem < 32) ? rem : 32;
        int myidx = (lane < cnt) ? idx[base + lane] : 0;
        int k = 0;
        for (; k + 4 <= cnt; k += 4) {
            int s0 = __shfl_sync(0xffffffffu, myidx, k);
            int s1 = __shfl_sync(0xffffffffu, myidx, k + 1);
            int s2 = __shfl_sync(0xffffffffu, myidx, k + 2);
            int s3 = __shfl_sync(0xffffffffu, myidx, k + 3);
            float2 v0 = __half22float2(hs2[s0 * 32 + lane]);
            float2 v1 = __half22float2(hs2[s1 * 32 + lane]);
            float2 v2 = __half22float2(hs2[s2 * 32 + lane]);
            float2 v3 = __half22float2(hs2[s3 * 32 + lane]);
            acc.x += (v0.x + v1.x) + (v2.x + v3.x);
            acc.y += (v0.y + v1.y) + (v2.y + v3.y);
        }
        for (; k < cnt; k++) {
            int s = __shfl_sync(0xffffffffu, myidx, k);
            float2 v = __half22float2(hs2[s * 32 + lane]);
            acc.x += v.x; acc.y += v.y;
        }
    }

    float dv = g_dinv[node];
    float ox = fmaxf(fmaf(acc.x * dv, scx, shx), 0.f);
    float oy = fmaxf(fmaf(acc.y * dv, scy, shy), 0.f);
    ((unsigned*)g_xh)[node * 32 + lane] = pack_half2(ox, oy);
}

// ---------------- gather layer 3 + FUSED POOLING (reads hsh2) ----------------
__global__ void __launch_bounds__(256) k_gather2(
        const int* __restrict__ bidx,
        const float* __restrict__ b, const float* __restrict__ gm,
        const float* __restrict__ be, const float* __restrict__ rm,
        const float* __restrict__ rv) {
    __shared__ float sval[8][64];
    __shared__ int   sgid[8];
    int lane = threadIdx.x & 31;
    int w = threadIdx.x >> 5;
    int node = blockIdx.x * 8 + w;

    int j = lane * 2;
    float scx = gm[j] * rsqrtf(rv[j] + BN_EPS);
    float scy = gm[j + 1] * rsqrtf(rv[j + 1] + BN_EPS);
    float shx = (b[j] - rm[j]) * scx + be[j];
    float shy = (b[j + 1] - rm[j + 1]) * scy + be[j + 1];

    const __half2* __restrict__ hs2 = g_hsh2;
    float2 acc = __half22float2(hs2[node * 32 + lane]);

    int beg = g_rowptr[node];
    int m = g_rowend[node] - beg;
    const int* __restrict__ idx = g_csrsrc + beg;

    for (int base = 0; base < m; base += 32) {
        int rem = m - base;
        int cnt = (rem < 32) ? rem : 32;
        int myidx = (lane < cnt) ? idx[base + lane] : 0;
        int k = 0;
        for (; k + 4 <= cnt; k += 4) {
            int s0 = __shfl_sync(0xffffffffu, myidx, k);
            int s1 = __shfl_sync(0xffffffffu, myidx, k + 1);
            int s2 = __shfl_sync(0xffffffffu, myidx, k + 2);
            int s3 = __shfl_sync(0xffffffffu, myidx, k + 3);
            float2 v0 = __half22float2(hs2[s0 * 32 + lane]);
            float2 v1 = __half22float2(hs2[s1 * 32 + lane]);
            float2 v2 = __half22float2(hs2[s2 * 32 + lane]);
            float2 v3 = __half22float2(hs2[s3 * 32 + lane]);
            acc.x += (v0.x + v1.x) + (v2.x + v3.x);
            acc.y += (v0.y + v1.y) + (v2.y + v3.y);
        }
        for (; k < cnt; k++) {
            int s = __shfl_sync(0xffffffffu, myidx, k);
            float2 v = __half22float2(hs2[s * 32 + lane]);
            acc.x += v.x; acc.y += v.y;
        }
    }

    float dv = g_dinv[node];
    sval[w][j]     = fmaxf(fmaf(acc.x * dv, scx, shx), 0.f);
    sval[w][j + 1] = fmaxf(fmaf(acc.y * dv, scy, shy), 0.f);
    if (lane == 0) sgid[w] = bidx[node];
    __syncthreads();

    int gid = sgid[w];
    bool leader = (w == 0) || (sgid[w - 1] != gid);
    if (leader) {
        float sx = 0.f, sy = 0.f, mxx = 0.f, mxy = 0.f;
        int c = 0;
        for (int s2 = w; s2 < 8 && sgid[s2] == gid; s2++) {
            float vx = sval[s2][j], vy = sval[s2][j + 1];
            sx += vx; sy += vy;
            mxx = fmaxf(mxx, vx); mxy = fmaxf(mxy, vy);
            c++;
        }
        atomicAdd(&g_gsum[gid * 64 + j], sx);
        atomicAdd(&g_gsum[gid * 64 + j + 1], sy);
        atomicMax(&g_gmax[gid * 64 + j], __float_as_int(mxx));
        atomicMax(&g_gmax[gid * 64 + j + 1], __float_as_int(mxy));
        if (lane == 0) atomicAdd(&g_gcnt[gid], (float)c);
    }
}

// ---------------- MLP head (+ cleanup of pooling accumulators) ----------------
__global__ void k_mlp(const float* __restrict__ mW1, const float* __restrict__ mb1,
                      const float* __restrict__ mW2, const float* __restrict__ mb2,
                      const float* __restrict__ mW3, const float* __restrict__ mb3,
                      float* __restrict__ out) {
    __shared__ float xg[128];
    __shared__ float h1[32];
    __shared__ float h2[16];
    int g = blockIdx.x;
    int t = threadIdx.x;                // 32 threads
    float cnt = fmaxf(g_gcnt[g], 1.f);
    for (int j = t; j < 64; j += 32) {
        xg[j]      = g_gsum[g * 64 + j] / cnt;
        xg[64 + j] = __int_as_float(g_gmax[g * 64 + j]);
    }
    __syncthreads();
    for (int j = t; j < 64; j += 32) {
        g_gsum[g * 64 + j] = 0.f;
        g_gmax[g * 64 + j] = 0;
    }
    if (t == 0) g_gcnt[g] = 0.f;
    {
        float acc = mb1[t];
        for (int k = 0; k < 128; k++) acc += xg[k] * mW1[k * 32 + t];
        h1[t] = fmaxf(acc, 0.f);
    }
    __syncthreads();
    if (t < 16) {
        float acc = mb2[t];
        for (int k = 0; k < 32; k++) acc += h1[k] * mW2[k * 16 + t];
        h2[t] = fmaxf(acc, 0.f);
    }
    __syncthreads();
    if (t == 0) {
        float acc = mb3[0];
        for (int k = 0; k < 16; k++) acc += h2[k] * mW3[k];
        out[g] = acc;
    }
}

extern "C" void kernel_launch(void* const* d_in, const int* in_sizes, int n_in,
                              void* d_out, int out_size) {
    const float* x    = (const float*)d_in[0];
    const int*   ei   = (const int*)  d_in[1];
    const int*   bidx = (const int*)  d_in[2];
    const float* W[3]  = {(const float*)d_in[3],  (const float*)d_in[9],  (const float*)d_in[15]};
    const float* b[3]  = {(const float*)d_in[4],  (const float*)d_in[10], (const float*)d_in[16]};
    const float* gm[3] = {(const float*)d_in[5],  (const float*)d_in[11], (const float*)d_in[17]};
    const float* be[3] = {(const float*)d_in[6],  (const float*)d_in[12], (const float*)d_in[18]};
    const float* rm[3] = {(const float*)d_in[7],  (const float*)d_in[13], (const float*)d_in[19]};
    const float* rv[3] = {(const float*)d_in[8],  (const float*)d_in[14], (const float*)d_in[20]};
    const float* mW1 = (const float*)d_in[21];
    const float* mb1 = (const float*)d_in[22];
    const float* mW2 = (const float*)d_in[23];
    const float* mb2 = (const float*)d_in[24];
    const float* mW3 = (const float*)d_in[25];
    const float* mb3 = (const float*)d_in[26];
    float* out = (float*)d_out;

    const int T = 256;
    int deg4Blocks = (EE / 4 + T - 1) / T;
    int nBlocks    = (NN + T - 1) / T;
    int l0Blocks   = (NN + 63) / 64;
    int tcBlocks   = (NN + 127) / 128;
    int gatBlocks  = NN / 8;            // NN % 8 == 0

    k_deg<<<deg4Blocks, T>>>(ei);
    k_alloc<<<nBlocks, T>>>(x);
    k_csr<<<deg4Blocks, T>>>(ei);

    k_layer0<<<l0Blocks, 256>>>(W[0], b[0], gm[0], be[0], rm[0], rv[0]);
    k_mm_tc<<<tcBlocks, 512>>>(W[1], 0);                       // g_xh -> hsh1
    k_gatherM<<<gatBlocks, T>>>(b[1], gm[1], be[1], rm[1], rv[1]);  // hsh1 -> g_xh
    k_mm_tc<<<tcBlocks, 512>>>(W[2], 1);                       // g_xh -> hsh2
    k_gather2<<<gatBlocks, T>>>(bidx, b[2], gm[2], be[2], rm[2], rv[2]);

    k_mlp<<<GG, 32>>>(mW1, mb1, mW2, mb2, mW3, mb3, out);
}